// round 15
// baseline (speedup 1.0000x reference)
#include <cuda_runtime.h>
#include <cuda_fp16.h>
#include <stdint.h>
#include <math.h>

#define BSZ  8
#define H    512
#define P    128
#define LSEQ 8192
#define K2   256          // 2P

// ---------------- scratch (__device__ globals; allocation-free rule) --------
__device__ __align__(16) __half g_uH[(size_t)BSZ * H * LSEQ];   // u fp16 [b][h][l]
__device__ __align__(16) __half g_Xh[(size_t)BSZ * K2 * LSEQ];  // Bu then xs, fp16 [b][2p][l]
__device__ __align__(16) __half g_W [K2 * H];                   // Bst fp16 [2p][h]
__device__ __align__(16) __half g_C [H * K2];                   // folded C fp16 [h][2p]
__device__ float2 g_Lbar[P];

// ---------------- helpers ---------------------------------------------------
__device__ __forceinline__ float2 cmul(float2 a, float2 b) {
    return make_float2(a.x * b.x - a.y * b.y, a.x * b.y + a.y * b.x);
}
__device__ __forceinline__ unsigned smem_u32(const void* p) {
    return (unsigned)__cvta_generic_to_shared(p);
}
__device__ __forceinline__ void cp16(unsigned s, const void* g) {
    asm volatile("cp.async.cg.shared.global [%0], [%1], 16;\n" :: "r"(s), "l"(g));
}
__device__ __forceinline__ void cp_commit() { asm volatile("cp.async.commit_group;\n"); }
__device__ __forceinline__ void cp_wait0()  { asm volatile("cp.async.wait_group 0;\n"); }
__device__ __forceinline__ void cp_wait1()  { asm volatile("cp.async.wait_group 1;\n"); }

#define LDSM_X4(r0, r1, r2, r3, a)                                              \
    asm volatile("ldmatrix.sync.aligned.m8n8.x4.shared.b16 {%0,%1,%2,%3}, [%4];"\
                 : "=r"(r0), "=r"(r1), "=r"(r2), "=r"(r3) : "r"(a))
#define LDSM_X4_T(r0, r1, r2, r3, a)                                            \
    asm volatile("ldmatrix.sync.aligned.m8n8.x4.trans.shared.b16 {%0,%1,%2,%3}, [%4];"\
                 : "=r"(r0), "=r"(r1), "=r"(r2), "=r"(r3) : "r"(a))

#define MMA16816(c, a, b)                                                       \
    asm volatile("mma.sync.aligned.m16n8k16.row.col.f32.f16.f16.f32 "           \
                 "{%0,%1,%2,%3}, {%4,%5,%6,%7}, {%8,%9}, {%0,%1,%2,%3};"        \
                 : "+f"((c)[0]), "+f"((c)[1]), "+f"((c)[2]), "+f"((c)[3])       \
                 : "r"((a)[0]), "r"((a)[1]), "r"((a)[2]), "r"((a)[3]),          \
                   "r"((b)[0]), "r"((b)[1]))

// A rows: 32 halfs = 64B + 16B pad = 80B stride (conflict-free ldmatrix)
// B tile: 32 k-rows x 136 halfs = 272B stride (conflict-free trans ldmatrix)

// ---------------------------------------------------------------------------
// Setup: Lambda_bar, fp16 stacked Bbar [2p][h], fp16 folded C [h][2p].
// ---------------------------------------------------------------------------
__global__ void setup_kernel(const float* __restrict__ Lre, const float* __restrict__ Lim,
                             const float* __restrict__ Bm, const float* __restrict__ Cm,
                             const float* __restrict__ logstep) {
    int tid = blockIdx.x * blockDim.x + threadIdx.x;
    int stride = gridDim.x * blockDim.x;

    if (tid < P) {
        double st = exp((double)logstep[tid]);
        double zre = (double)Lre[tid] * st, zim = (double)Lim[tid] * st;
        double er = exp(zre);
        g_Lbar[tid] = make_float2((float)(er * cos(zim)), (float)(er * sin(zim)));
    }

    for (int i = tid; i < P * H; i += stride) {
        int p = i >> 9, h = i & (H - 1);
        double st  = exp((double)logstep[p]);
        double lre = (double)Lre[p], lim = (double)Lim[p];
        double zre = lre * st, zim = lim * st;
        double er  = exp(zre);
        double numr = er * cos(zim) - 1.0;
        double numi = er * sin(zim);
        double den  = lre * lre + lim * lim;
        double gre = (numr * lre + numi * lim) / den;
        double gim = (numi * lre - numr * lim) / den;
        float br = Bm[2 * i], bi = Bm[2 * i + 1];
        float vre = (float)(gre * (double)br - gim * (double)bi);
        float vim = (float)(gre * (double)bi + gim * (double)br);
        g_W[p * H + h]       = __float2half_rn(vre);
        g_W[(P + p) * H + h] = __float2half_rn(vim);
    }

    for (int i = tid; i < H * K2; i += stride) {
        int h = i >> 8, k = i & (K2 - 1);
        float v = (k < P) ? 2.0f * Cm[(h * P + k) * 2]
                          : -2.0f * Cm[(h * P + (k - P)) * 2 + 1];
        g_C[(size_t)h * K2 + k] = __float2half_rn(v);
    }
}

// ---------------------------------------------------------------------------
// u fp32 -> fp16, same layout (elementwise, fully coalesced).
// ---------------------------------------------------------------------------
__global__ void __launch_bounds__(256) uconv_kernel(const float* __restrict__ u) {
    size_t i = ((size_t)blockIdx.x * 256 + threadIdx.x) * 8;
    float4 a = *(const float4*)(u + i);
    float4 b = *(const float4*)(u + i + 4);
    __half2 h[4];
    h[0] = __floats2half2_rn(a.x, a.y);
    h[1] = __floats2half2_rn(a.z, a.w);
    h[2] = __floats2half2_rn(b.x, b.y);
    h[3] = __floats2half2_rn(b.z, b.w);
    *(uint4*)(g_uH + i) = *(uint4*)h;
}

// ---------------------------------------------------------------------------
// Shared MMA mainloop: C[MROWS x 128] = W[MROWS x KD] * Bg[KD x 128] (fp16),
// W K-major, Bg natural [k][L] via ldmatrix.trans.
// 8 warps as 4(m) x 2(n); warp tile (MT*16) x 64. 2-stage cp.async pipeline
// with compile-time stage addressing ((ch&1)*STG -> unrolled, folded addrs).
// ---------------------------------------------------------------------------
template <int KD, int MROWS, int MT>
__device__ __forceinline__ void mma_mainloop(
    const __half* __restrict__ W,
    const __half* __restrict__ Bg, int l0,
    unsigned sbase, int tid, int wid, int lane, float c[MT][8][4])
{
    constexpr int AB   = MROWS * 80;
    constexpr int BOFF = AB;
    constexpr int STG  = BOFF + 32 * 272;
    const int wr = wid >> 1, wc = wid & 1;
    const int m0w = wr * (MT * 16);
    const int n0w = wc * 64;
    constexpr int NCH = KD / 32;

    auto load_stage = [&](int buf, int k0) {
        unsigned sb = sbase + buf * STG;
        for (int s = tid; s < MROWS * 4; s += 256) {
            int r = s >> 2, seg = s & 3;
            cp16(sb + r * 80 + seg * 16, W + (size_t)r * KD + k0 + seg * 8);
        }
        for (int s = tid; s < 512; s += 256) {
            int r = s >> 4, seg = s & 15;
            cp16(sb + BOFF + r * 272 + seg * 16,
                 Bg + (size_t)(k0 + r) * LSEQ + l0 + seg * 8);
        }
        cp_commit();
    };

    load_stage(0, 0);
    load_stage(1, 32);

    for (int ch = 0; ch < NCH; ch++) {
        if (ch < NCH - 1) cp_wait1(); else cp_wait0();
        __syncthreads();
        unsigned sb = sbase + (ch & 1) * STG;

#pragma unroll
        for (int ks = 0; ks < 2; ks++) {
            unsigned aH[MT][4];
            unsigned koff = ks * 32 + (lane >> 4) * 16;
#pragma unroll
            for (int mt = 0; mt < MT; mt++) {
                unsigned ra = sb + (m0w + mt * 16 + (lane & 15)) * 80 + koff;
                LDSM_X4(aH[mt][0], aH[mt][1], aH[mt][2], aH[mt][3], ra);
            }
            unsigned b[8][2];
#pragma unroll
            for (int np = 0; np < 4; np++) {
                unsigned rb = sb + BOFF + (ks * 16 + (lane & 15)) * 272
                            + (n0w + np * 16 + (lane >> 4) * 8) * 2;
                unsigned t0, t1, t2, t3;
                LDSM_X4_T(t0, t1, t2, t3, rb);
                b[2 * np][0]     = t0; b[2 * np][1]     = t1;
                b[2 * np + 1][0] = t2; b[2 * np + 1][1] = t3;
            }
#pragma unroll
            for (int mt = 0; mt < MT; mt++)
#pragma unroll
                for (int nt = 0; nt < 8; nt++)
                    MMA16816(c[mt][nt], aH[mt], b[nt]);
        }
        __syncthreads();
        if (ch + 2 < NCH) load_stage(ch & 1, (ch + 2) * 32);
    }
}

#define SMEM_K1 (2 * (256 * 80 + 32 * 272))   // 58368
#define SMEM_K3 (2 * (128 * 80 + 32 * 272))   // 37888

// ---------------------------------------------------------------------------
// K1: Bu planes. C[2p(256) x l(128)] = Bst * u. fp16 plane writes into g_Xh.
// ---------------------------------------------------------------------------
__global__ void __launch_bounds__(256, 1) bu_mma_kernel() {
    extern __shared__ __align__(16) char dsm[];
    const unsigned sbase = smem_u32(dsm);
    const int b = blockIdx.z, l0 = blockIdx.x * 128;
    const int tid = threadIdx.x, wid = tid >> 5, lane = tid & 31;

    float c[4][8][4] = {};
    mma_mainloop<H, 256, 4>(g_W, g_uH + (size_t)b * H * LSEQ,
                            l0, sbase, tid, wid, lane, c);

    const int wr = wid >> 1, wc = wid & 1;
    const int m0w = wr * 64, n0w = wc * 64;
#pragma unroll
    for (int mt = 0; mt < 4; mt++)
#pragma unroll
        for (int nt = 0; nt < 8; nt++) {
            int row = m0w + mt * 16 + (lane >> 2);
            int col = n0w + nt * 8 + (lane & 3) * 2;
            __half* dst = g_Xh + ((size_t)b * K2 + row) * LSEQ + l0 + col;
            *(__half2*)dst = __floats2half2_rn(c[mt][nt][0], c[mt][nt][1]);
            *(__half2*)(dst + (size_t)8 * LSEQ) = __floats2half2_rn(c[mt][nt][2], c[mt][nt][3]);
        }
}

// ---------------------------------------------------------------------------
// K3: out. C[h(128) x l(128)] = C2 * xs; epilogue + D*u(fp16) + exact gelu.
// ---------------------------------------------------------------------------
__global__ void __launch_bounds__(256, 1) out_mma_kernel(const float* __restrict__ Dv,
                                                         float* __restrict__ out) {
    extern __shared__ __align__(16) char dsm[];
    const unsigned sbase = smem_u32(dsm);
    const int b = blockIdx.z, l0 = blockIdx.x * 128, h0 = blockIdx.y * 128;
    const int tid = threadIdx.x, wid = tid >> 5, lane = tid & 31;

    float c[2][8][4] = {};
    mma_mainloop<K2, 128, 2>(g_C + (size_t)h0 * K2,
                             g_Xh + (size_t)b * K2 * LSEQ,
                             l0, sbase, tid, wid, lane, c);

    const int wr = wid >> 1, wc = wid & 1;
    const int m0w = wr * 32, n0w = wc * 64;
#pragma unroll
    for (int mt = 0; mt < 2; mt++)
#pragma unroll
        for (int nt = 0; nt < 8; nt++) {
            int row = m0w + mt * 16 + (lane >> 2);
            int col = n0w + nt * 8 + (lane & 3) * 2;
            int h = h0 + row;
            size_t o = ((size_t)b * H + h) * LSEQ + l0 + col;

            float2 uv = __half22float2(*(const __half2*)(g_uH + o));
            float dd = Dv[h];
            float v0 = c[mt][nt][0] + dd * uv.x;
            float v1 = c[mt][nt][1] + dd * uv.y;
            v0 = 0.5f * v0 * (1.0f + erff(v0 * 0.70710678118654752f));
            v1 = 0.5f * v1 * (1.0f + erff(v1 * 0.70710678118654752f));
            *(float2*)(out + o) = make_float2(v0, v1);

            size_t o2 = o + (size_t)8 * LSEQ;
            float2 uw = __half22float2(*(const __half2*)(g_uH + o2));
            float de = Dv[h + 8];
            float v2 = c[mt][nt][2] + de * uw.x;
            float v3 = c[mt][nt][3] + de * uw.y;
            v2 = 0.5f * v2 * (1.0f + erff(v2 * 0.70710678118654752f));
            v3 = 0.5f * v3 * (1.0f + erff(v3 * 0.70710678118654752f));
            *(float2*)(out + o2) = make_float2(v2, v3);
        }
}

// ---------------------------------------------------------------------------
// Scan along L per (b,p); warp-shuffle Kogge-Stone; fp16 planes in-place
// (fp32 arithmetic internally).
// ---------------------------------------------------------------------------
__global__ void __launch_bounds__(512) scan_kernel() {
    const int seq = blockIdx.x;          // b*P + p
    const int b   = seq >> 7;
    const int p   = seq & (P - 1);
    const float2 a = g_Lbar[p];
    const int t = threadIdx.x;
    const int lane = t & 31, w = t >> 5;

    __half* pre = g_Xh + ((size_t)b * K2 + p) * LSEQ + t * 16;
    __half* pim = g_Xh + ((size_t)b * K2 + P + p) * LSEQ + t * 16;

    __half2 hre[8], him[8];
    ((uint4*)hre)[0] = ((const uint4*)pre)[0];
    ((uint4*)hre)[1] = ((const uint4*)pre)[1];
    ((uint4*)him)[0] = ((const uint4*)pim)[0];
    ((uint4*)him)[1] = ((const uint4*)pim)[1];

    float2 x[16];
#pragma unroll
    for (int j = 0; j < 8; j++) {
        float2 r = __half22float2(hre[j]);
        float2 i = __half22float2(him[j]);
        x[2 * j]     = make_float2(r.x, i.x);
        x[2 * j + 1] = make_float2(r.y, i.y);
    }

    float2 v = make_float2(0.f, 0.f);
#pragma unroll
    for (int j = 0; j < 16; j++) {
        float2 av = cmul(a, v);
        v = make_float2(av.x + x[j].x, av.y + x[j].y);
        x[j] = v;
    }

    float2 a16 = cmul(a, a); a16 = cmul(a16, a16); a16 = cmul(a16, a16); a16 = cmul(a16, a16);

    float2 f = a16;
    float2 vi2 = v;
#pragma unroll
    for (int d = 1; d < 32; d <<= 1) {
        float px = __shfl_up_sync(0xffffffffu, vi2.x, d);
        float py = __shfl_up_sync(0xffffffffu, vi2.y, d);
        if (lane >= d) {
            float2 add = cmul(f, make_float2(px, py));
            vi2.x += add.x; vi2.y += add.y;
        }
        f = cmul(f, f);
    }
    float ex = __shfl_up_sync(0xffffffffu, vi2.x, 1);
    float ey = __shfl_up_sync(0xffffffffu, vi2.y, 1);
    float2 vex = (lane == 0) ? make_float2(0.f, 0.f) : make_float2(ex, ey);

    __shared__ float2 wsum[16];
    __shared__ float2 wpre[16];
    if (lane == 31) wsum[w] = vi2;
    __syncthreads();

    float2 a512 = cmul(a16, a16); a512 = cmul(a512, a512); a512 = cmul(a512, a512);
    a512 = cmul(a512, a512); a512 = cmul(a512, a512);

    if (w == 0) {
        float2 s = (lane < 16) ? wsum[lane] : make_float2(0.f, 0.f);
        float2 g = a512;
#pragma unroll
        for (int d = 1; d < 16; d <<= 1) {
            float px = __shfl_up_sync(0xffffffffu, s.x, d);
            float py = __shfl_up_sync(0xffffffffu, s.y, d);
            if (lane >= d) {
                float2 add = cmul(g, make_float2(px, py));
                s.x += add.x; s.y += add.y;
            }
            g = cmul(g, g);
        }
        float qx = __shfl_up_sync(0xffffffffu, s.x, 1);
        float qy = __shfl_up_sync(0xffffffffu, s.y, 1);
        if (lane < 16) wpre[lane] = (lane == 0) ? make_float2(0.f, 0.f) : make_float2(qx, qy);
    }
    __syncthreads();

    float2 pw16 = make_float2(1.f, 0.f);
    {
        float2 base = a16; int e = lane;
#pragma unroll
        for (int it = 0; it < 5; it++) {
            if (e & 1) pw16 = cmul(pw16, base);
            base = cmul(base, base);
            e >>= 1;
        }
    }
    float2 wc = wpre[w];
    float2 s0 = cmul(pw16, wc);
    s0.x += vex.x; s0.y += vex.y;

    float2 pw = a;
#pragma unroll
    for (int j = 0; j < 16; j++) {
        float2 add = cmul(pw, s0);
        x[j].x += add.x; x[j].y += add.y;
        pw = cmul(pw, a);
    }

#pragma unroll
    for (int j = 0; j < 8; j++) {
        hre[j] = __floats2half2_rn(x[2 * j].x, x[2 * j + 1].x);
        him[j] = __floats2half2_rn(x[2 * j].y, x[2 * j + 1].y);
    }
    ((uint4*)pre)[0] = ((uint4*)hre)[0];
    ((uint4*)pre)[1] = ((uint4*)hre)[1];
    ((uint4*)pim)[0] = ((uint4*)him)[0];
    ((uint4*)pim)[1] = ((uint4*)him)[1];
}

// ---------------------------------------------------------------------------
extern "C" void kernel_launch(void* const* d_in, const int* in_sizes, int n_in,
                              void* d_out, int out_size) {
    const float* u   = (const float*)d_in[0];
    const float* Lre = (const float*)d_in[1];
    const float* Lim = (const float*)d_in[2];
    const float* Bm  = (const float*)d_in[3];
    const float* Cm  = (const float*)d_in[4];
    const float* D   = (const float*)d_in[5];
    const float* ls  = (const float*)d_in[6];
    float* out = (float*)d_out;

    cudaFuncSetAttribute(bu_mma_kernel,  cudaFuncAttributeMaxDynamicSharedMemorySize, SMEM_K1);
    cudaFuncSetAttribute(out_mma_kernel, cudaFuncAttributeMaxDynamicSharedMemorySize, SMEM_K3);

    setup_kernel<<<256, 256>>>(Lre, Lim, Bm, Cm, ls);

    uconv_kernel<<<(unsigned)((size_t)BSZ * H * LSEQ / (256 * 8)), 256>>>(u);

    bu_mma_kernel<<<dim3(LSEQ / 128, 1, BSZ), 256, SMEM_K1>>>();

    scan_kernel<<<BSZ * P, 512>>>();

    out_mma_kernel<<<dim3(LSEQ / 128, 4, BSZ), 256, SMEM_K3>>>(D, out);
}

// round 16
// speedup vs baseline: 1.1873x; 1.1873x over previous
#include <cuda_runtime.h>
#include <cuda_fp16.h>
#include <stdint.h>
#include <math.h>

#define BSZ  8
#define H    512
#define P    128
#define LSEQ 8192
#define K2   256          // 2P

// ---------------- scratch (__device__ globals; allocation-free rule) --------
__device__ __align__(16) __half g_uH[(size_t)BSZ * H * LSEQ];   // u fp16 [b][h][l]
__device__ __align__(16) __half g_Xh[(size_t)BSZ * K2 * LSEQ];  // Bu then xs, fp16 [b][2p][l]
__device__ __align__(16) __half g_W [K2 * H];                   // Bst fp16 [2p][h]
__device__ __align__(16) __half g_C [H * K2];                   // folded C fp16 [h][2p]
__device__ float2 g_Lbar[P];

// ---------------- helpers ---------------------------------------------------
__device__ __forceinline__ float2 cmul(float2 a, float2 b) {
    return make_float2(a.x * b.x - a.y * b.y, a.x * b.y + a.y * b.x);
}
__device__ __forceinline__ unsigned smem_u32(const void* p) {
    return (unsigned)__cvta_generic_to_shared(p);
}
__device__ __forceinline__ void cp16(unsigned s, const void* g) {
    asm volatile("cp.async.cg.shared.global [%0], [%1], 16;\n" :: "r"(s), "l"(g));
}
__device__ __forceinline__ void cp_commit() { asm volatile("cp.async.commit_group;\n"); }
__device__ __forceinline__ void cp_wait0()  { asm volatile("cp.async.wait_group 0;\n"); }
__device__ __forceinline__ void cp_wait1()  { asm volatile("cp.async.wait_group 1;\n"); }

#define LDSM_X4(r0, r1, r2, r3, a)                                              \
    asm volatile("ldmatrix.sync.aligned.m8n8.x4.shared.b16 {%0,%1,%2,%3}, [%4];"\
                 : "=r"(r0), "=r"(r1), "=r"(r2), "=r"(r3) : "r"(a))
#define LDSM_X4_T(r0, r1, r2, r3, a)                                            \
    asm volatile("ldmatrix.sync.aligned.m8n8.x4.trans.shared.b16 {%0,%1,%2,%3}, [%4];"\
                 : "=r"(r0), "=r"(r1), "=r"(r2), "=r"(r3) : "r"(a))

#define MMA16816(c, a, b)                                                       \
    asm volatile("mma.sync.aligned.m16n8k16.row.col.f32.f16.f16.f32 "           \
                 "{%0,%1,%2,%3}, {%4,%5,%6,%7}, {%8,%9}, {%0,%1,%2,%3};"        \
                 : "+f"((c)[0]), "+f"((c)[1]), "+f"((c)[2]), "+f"((c)[3])       \
                 : "r"((a)[0]), "r"((a)[1]), "r"((a)[2]), "r"((a)[3]),          \
                   "r"((b)[0]), "r"((b)[1]))

// A rows: 32 halfs = 64B + 16B pad = 80B stride (conflict-free ldmatrix)
// B tile: 32 k-rows x 136 halfs = 272B stride (conflict-free trans ldmatrix)

// ---------------------------------------------------------------------------
// Setup: Lambda_bar, fp16 stacked Bbar [2p][h], fp16 folded C [h][2p].
// ---------------------------------------------------------------------------
__global__ void setup_kernel(const float* __restrict__ Lre, const float* __restrict__ Lim,
                             const float* __restrict__ Bm, const float* __restrict__ Cm,
                             const float* __restrict__ logstep) {
    int tid = blockIdx.x * blockDim.x + threadIdx.x;
    int stride = gridDim.x * blockDim.x;

    if (tid < P) {
        double st = exp((double)logstep[tid]);
        double zre = (double)Lre[tid] * st, zim = (double)Lim[tid] * st;
        double er = exp(zre);
        g_Lbar[tid] = make_float2((float)(er * cos(zim)), (float)(er * sin(zim)));
    }

    for (int i = tid; i < P * H; i += stride) {
        int p = i >> 9, h = i & (H - 1);
        double st  = exp((double)logstep[p]);
        double lre = (double)Lre[p], lim = (double)Lim[p];
        double zre = lre * st, zim = lim * st;
        double er  = exp(zre);
        double numr = er * cos(zim) - 1.0;
        double numi = er * sin(zim);
        double den  = lre * lre + lim * lim;
        double gre = (numr * lre + numi * lim) / den;
        double gim = (numi * lre - numr * lim) / den;
        float br = Bm[2 * i], bi = Bm[2 * i + 1];
        float vre = (float)(gre * (double)br - gim * (double)bi);
        float vim = (float)(gre * (double)bi + gim * (double)br);
        g_W[p * H + h]       = __float2half_rn(vre);
        g_W[(P + p) * H + h] = __float2half_rn(vim);
    }

    for (int i = tid; i < H * K2; i += stride) {
        int h = i >> 8, k = i & (K2 - 1);
        float v = (k < P) ? 2.0f * Cm[(h * P + k) * 2]
                          : -2.0f * Cm[(h * P + (k - P)) * 2 + 1];
        g_C[(size_t)h * K2 + k] = __float2half_rn(v);
    }
}

// ---------------------------------------------------------------------------
// u fp32 -> fp16, same layout (elementwise, fully coalesced).
// ---------------------------------------------------------------------------
__global__ void __launch_bounds__(256) uconv_kernel(const float* __restrict__ u) {
    size_t i = ((size_t)blockIdx.x * 256 + threadIdx.x) * 8;
    float4 a = *(const float4*)(u + i);
    float4 b = *(const float4*)(u + i + 4);
    __half2 h[4];
    h[0] = __floats2half2_rn(a.x, a.y);
    h[1] = __floats2half2_rn(a.z, a.w);
    h[2] = __floats2half2_rn(b.x, b.y);
    h[3] = __floats2half2_rn(b.z, b.w);
    *(uint4*)(g_uH + i) = *(uint4*)h;
}

// ---------------------------------------------------------------------------
// Shared MMA mainloop: C[MROWS x 128] = W[MROWS x KD] * Bg[KD x 128] (fp16),
// W K-major, Bg natural [k][L] via ldmatrix.trans.
// 8 warps as 4(m) x 2(n); warp tile (MT*16) x 64. 2-stage cp.async pipeline
// with compile-time stage addressing ((ch&1)*STG -> unrolled, folded addrs).
// ---------------------------------------------------------------------------
template <int KD, int MROWS, int MT>
__device__ __forceinline__ void mma_mainloop(
    const __half* __restrict__ W,
    const __half* __restrict__ Bg, int l0,
    unsigned sbase, int tid, int wid, int lane, float c[MT][8][4])
{
    constexpr int AB   = MROWS * 80;
    constexpr int BOFF = AB;
    constexpr int STG  = BOFF + 32 * 272;
    const int wr = wid >> 1, wc = wid & 1;
    const int m0w = wr * (MT * 16);
    const int n0w = wc * 64;
    constexpr int NCH = KD / 32;

    auto load_stage = [&](int buf, int k0) {
        unsigned sb = sbase + buf * STG;
        for (int s = tid; s < MROWS * 4; s += 256) {
            int r = s >> 2, seg = s & 3;
            cp16(sb + r * 80 + seg * 16, W + (size_t)r * KD + k0 + seg * 8);
        }
        for (int s = tid; s < 512; s += 256) {
            int r = s >> 4, seg = s & 15;
            cp16(sb + BOFF + r * 272 + seg * 16,
                 Bg + (size_t)(k0 + r) * LSEQ + l0 + seg * 8);
        }
        cp_commit();
    };

    load_stage(0, 0);
    load_stage(1, 32);

    for (int ch = 0; ch < NCH; ch++) {
        if (ch < NCH - 1) cp_wait1(); else cp_wait0();
        __syncthreads();
        unsigned sb = sbase + (ch & 1) * STG;

#pragma unroll
        for (int ks = 0; ks < 2; ks++) {
            unsigned aH[MT][4];
            unsigned koff = ks * 32 + (lane >> 4) * 16;
#pragma unroll
            for (int mt = 0; mt < MT; mt++) {
                unsigned ra = sb + (m0w + mt * 16 + (lane & 15)) * 80 + koff;
                LDSM_X4(aH[mt][0], aH[mt][1], aH[mt][2], aH[mt][3], ra);
            }
            unsigned b[8][2];
#pragma unroll
            for (int np = 0; np < 4; np++) {
                unsigned rb = sb + BOFF + (ks * 16 + (lane & 15)) * 272
                            + (n0w + np * 16 + (lane >> 4) * 8) * 2;
                unsigned t0, t1, t2, t3;
                LDSM_X4_T(t0, t1, t2, t3, rb);
                b[2 * np][0]     = t0; b[2 * np][1]     = t1;
                b[2 * np + 1][0] = t2; b[2 * np + 1][1] = t3;
            }
#pragma unroll
            for (int mt = 0; mt < MT; mt++)
#pragma unroll
                for (int nt = 0; nt < 8; nt++)
                    MMA16816(c[mt][nt], aH[mt], b[nt]);
        }
        __syncthreads();
        if (ch + 2 < NCH) load_stage(ch & 1, (ch + 2) * 32);
    }
}

#define SMEM_PIPE_K1 (2 * (256 * 80 + 32 * 272))   // 58368
#define SMEM_K1      69632                         // max(pipeline, 256*272 staging)
#define SMEM_K3      (2 * (128 * 80 + 32 * 272))   // 37888

// ---------------------------------------------------------------------------
// K1: Bu planes. C[2p(256) x l(128)] = Bst * u. fp16 output staged through
// smem (stride 272B, conflict-free) then written as full-sector 256B rows.
// ---------------------------------------------------------------------------
__global__ void __launch_bounds__(256, 1) bu_mma_kernel() {
    extern __shared__ __align__(16) char dsm[];
    const unsigned sbase = smem_u32(dsm);
    const int b = blockIdx.z, l0 = blockIdx.x * 128;
    const int tid = threadIdx.x, wid = tid >> 5, lane = tid & 31;

    float c[4][8][4] = {};
    mma_mainloop<H, 256, 4>(g_W, g_uH + (size_t)b * H * LSEQ,
                            l0, sbase, tid, wid, lane, c);

    // stage fp16 C tile in smem: row stride 136 halfs (272B)
    __half* cs = (__half*)dsm;
    const int wr = wid >> 1, wc = wid & 1;
    const int m0w = wr * 64, n0w = wc * 64;
#pragma unroll
    for (int mt = 0; mt < 4; mt++)
#pragma unroll
        for (int nt = 0; nt < 8; nt++) {
            int row = m0w + mt * 16 + (lane >> 2);
            int col = n0w + nt * 8 + (lane & 3) * 2;
            *(__half2*)(cs + row * 136 + col) =
                __floats2half2_rn(c[mt][nt][0], c[mt][nt][1]);
            *(__half2*)(cs + (row + 8) * 136 + col) =
                __floats2half2_rn(c[mt][nt][2], c[mt][nt][3]);
        }
    __syncthreads();

    // coalesced write-out: 256 rows x 256B, 16B per thread-segment
#pragma unroll
    for (int i = 0; i < 16; i++) {
        int idx = tid + i * 256;
        int row = idx >> 4, seg = idx & 15;
        uint4 v = *(uint4*)(cs + row * 136 + seg * 8);
        *(uint4*)(g_Xh + ((size_t)b * K2 + row) * LSEQ + l0 + seg * 8) = v;
    }
}

// ---------------------------------------------------------------------------
// K3: out. C[h(128) x l(128)] = C2 * xs; epilogue + D*u(fp32) + exact gelu.
// (byte-for-byte the round-11 known-good version)
// ---------------------------------------------------------------------------
__global__ void __launch_bounds__(256, 1) out_mma_kernel(const float* __restrict__ u,
                                                         const float* __restrict__ Dv,
                                                         float* __restrict__ out) {
    extern __shared__ __align__(16) char dsm[];
    const unsigned sbase = smem_u32(dsm);
    const int b = blockIdx.z, l0 = blockIdx.x * 128, h0 = blockIdx.y * 128;
    const int tid = threadIdx.x, wid = tid >> 5, lane = tid & 31;

    float c[2][8][4] = {};
    mma_mainloop<K2, 128, 2>(g_C + (size_t)h0 * K2,
                             g_Xh + (size_t)b * K2 * LSEQ,
                             l0, sbase, tid, wid, lane, c);

    const int wr = wid >> 1, wc = wid & 1;
    const int m0w = wr * 32, n0w = wc * 64;
#pragma unroll
    for (int mt = 0; mt < 2; mt++)
#pragma unroll
        for (int nt = 0; nt < 8; nt++) {
            int row = m0w + mt * 16 + (lane >> 2);
            int col = n0w + nt * 8 + (lane & 3) * 2;
            int h = h0 + row;
            size_t o = ((size_t)b * H + h) * LSEQ + l0 + col;

            float2 uv = *(const float2*)(u + o);
            float dd = Dv[h];
            float v0 = c[mt][nt][0] + dd * uv.x;
            float v1 = c[mt][nt][1] + dd * uv.y;
            v0 = 0.5f * v0 * (1.0f + erff(v0 * 0.70710678118654752f));
            v1 = 0.5f * v1 * (1.0f + erff(v1 * 0.70710678118654752f));
            *(float2*)(out + o) = make_float2(v0, v1);

            size_t o2 = o + (size_t)8 * LSEQ;
            float2 uw = *(const float2*)(u + o2);
            float de = Dv[h + 8];
            float v2 = c[mt][nt][2] + de * uw.x;
            float v3 = c[mt][nt][3] + de * uw.y;
            v2 = 0.5f * v2 * (1.0f + erff(v2 * 0.70710678118654752f));
            v3 = 0.5f * v3 * (1.0f + erff(v3 * 0.70710678118654752f));
            *(float2*)(out + o2) = make_float2(v2, v3);
        }
}

// ---------------------------------------------------------------------------
// Scan along L per (b,p); warp-shuffle Kogge-Stone; fp16 planes in-place
// (fp32 arithmetic internally).
// ---------------------------------------------------------------------------
__global__ void __launch_bounds__(512) scan_kernel() {
    const int seq = blockIdx.x;          // b*P + p
    const int b   = seq >> 7;
    const int p   = seq & (P - 1);
    const float2 a = g_Lbar[p];
    const int t = threadIdx.x;
    const int lane = t & 31, w = t >> 5;

    __half* pre = g_Xh + ((size_t)b * K2 + p) * LSEQ + t * 16;
    __half* pim = g_Xh + ((size_t)b * K2 + P + p) * LSEQ + t * 16;

    __half2 hre[8], him[8];
    ((uint4*)hre)[0] = ((const uint4*)pre)[0];
    ((uint4*)hre)[1] = ((const uint4*)pre)[1];
    ((uint4*)him)[0] = ((const uint4*)pim)[0];
    ((uint4*)him)[1] = ((const uint4*)pim)[1];

    float2 x[16];
#pragma unroll
    for (int j = 0; j < 8; j++) {
        float2 r = __half22float2(hre[j]);
        float2 i = __half22float2(him[j]);
        x[2 * j]     = make_float2(r.x, i.x);
        x[2 * j + 1] = make_float2(r.y, i.y);
    }

    float2 v = make_float2(0.f, 0.f);
#pragma unroll
    for (int j = 0; j < 16; j++) {
        float2 av = cmul(a, v);
        v = make_float2(av.x + x[j].x, av.y + x[j].y);
        x[j] = v;
    }

    float2 a16 = cmul(a, a); a16 = cmul(a16, a16); a16 = cmul(a16, a16); a16 = cmul(a16, a16);

    float2 f = a16;
    float2 vi2 = v;
#pragma unroll
    for (int d = 1; d < 32; d <<= 1) {
        float px = __shfl_up_sync(0xffffffffu, vi2.x, d);
        float py = __shfl_up_sync(0xffffffffu, vi2.y, d);
        if (lane >= d) {
            float2 add = cmul(f, make_float2(px, py));
            vi2.x += add.x; vi2.y += add.y;
        }
        f = cmul(f, f);
    }
    float ex = __shfl_up_sync(0xffffffffu, vi2.x, 1);
    float ey = __shfl_up_sync(0xffffffffu, vi2.y, 1);
    float2 vex = (lane == 0) ? make_float2(0.f, 0.f) : make_float2(ex, ey);

    __shared__ float2 wsum[16];
    __shared__ float2 wpre[16];
    if (lane == 31) wsum[w] = vi2;
    __syncthreads();

    float2 a512 = cmul(a16, a16); a512 = cmul(a512, a512); a512 = cmul(a512, a512);
    a512 = cmul(a512, a512); a512 = cmul(a512, a512);

    if (w == 0) {
        float2 s = (lane < 16) ? wsum[lane] : make_float2(0.f, 0.f);
        float2 g = a512;
#pragma unroll
        for (int d = 1; d < 16; d <<= 1) {
            float px = __shfl_up_sync(0xffffffffu, s.x, d);
            float py = __shfl_up_sync(0xffffffffu, s.y, d);
            if (lane >= d) {
                float2 add = cmul(g, make_float2(px, py));
                s.x += add.x; s.y += add.y;
            }
            g = cmul(g, g);
        }
        float qx = __shfl_up_sync(0xffffffffu, s.x, 1);
        float qy = __shfl_up_sync(0xffffffffu, s.y, 1);
        if (lane < 16) wpre[lane] = (lane == 0) ? make_float2(0.f, 0.f) : make_float2(qx, qy);
    }
    __syncthreads();

    float2 pw16 = make_float2(1.f, 0.f);
    {
        float2 base = a16; int e = lane;
#pragma unroll
        for (int it = 0; it < 5; it++) {
            if (e & 1) pw16 = cmul(pw16, base);
            base = cmul(base, base);
            e >>= 1;
        }
    }
    float2 wc = wpre[w];
    float2 s0 = cmul(pw16, wc);
    s0.x += vex.x; s0.y += vex.y;

    float2 pw = a;
#pragma unroll
    for (int j = 0; j < 16; j++) {
        float2 add = cmul(pw, s0);
        x[j].x += add.x; x[j].y += add.y;
        pw = cmul(pw, a);
    }

#pragma unroll
    for (int j = 0; j < 8; j++) {
        hre[j] = __floats2half2_rn(x[2 * j].x, x[2 * j + 1].x);
        him[j] = __floats2half2_rn(x[2 * j].y, x[2 * j + 1].y);
    }
    ((uint4*)pre)[0] = ((uint4*)hre)[0];
    ((uint4*)pre)[1] = ((uint4*)hre)[1];
    ((uint4*)pim)[0] = ((uint4*)him)[0];
    ((uint4*)pim)[1] = ((uint4*)him)[1];
}

// ---------------------------------------------------------------------------
extern "C" void kernel_launch(void* const* d_in, const int* in_sizes, int n_in,
                              void* d_out, int out_size) {
    const float* u   = (const float*)d_in[0];
    const float* Lre = (const float*)d_in[1];
    const float* Lim = (const float*)d_in[2];
    const float* Bm  = (const float*)d_in[3];
    const float* Cm  = (const float*)d_in[4];
    const float* D   = (const float*)d_in[5];
    const float* ls  = (const float*)d_in[6];
    float* out = (float*)d_out;

    cudaFuncSetAttribute(bu_mma_kernel,  cudaFuncAttributeMaxDynamicSharedMemorySize, SMEM_K1);
    cudaFuncSetAttribute(out_mma_kernel, cudaFuncAttributeMaxDynamicSharedMemorySize, SMEM_K3);

    setup_kernel<<<256, 256>>>(Lre, Lim, Bm, Cm, ls);

    uconv_kernel<<<(unsigned)((size_t)BSZ * H * LSEQ / (256 * 8)), 256>>>(u);

    bu_mma_kernel<<<dim3(LSEQ / 128, 1, BSZ), 256, SMEM_K1>>>();

    scan_kernel<<<BSZ * P, 512>>>();

    out_mma_kernel<<<dim3(LSEQ / 128, 4, BSZ), 256, SMEM_K3>>>(u, D, out);
}